// round 5
// baseline (speedup 1.0000x reference)
#include <cuda_runtime.h>
#include <cuda_bf16.h>
#include <math.h>
#include <stdint.h>

#define NB 8
#define HH 128
#define WW 128
#define NC 192
#define C3 576
#define HEADS 4
#define CH 48
#define HW 16384
#define BNT 32
#define KDIM 192

// ---------------- scratch ----------------
__device__ float g_qkv[(size_t)NB * HW * C3];
__device__ __nv_bfloat16 g_qh[(size_t)NB * HW * NC];
__device__ __nv_bfloat16 g_ql[(size_t)NB * HW * NC];
__device__ __nv_bfloat16 g_kh[(size_t)NB * HW * NC];
__device__ __nv_bfloat16 g_kl[(size_t)NB * HW * NC];
__device__ float g_v[(size_t)NB * HW * NC];
__device__ float g_o[(size_t)NB * HW * NC];
__device__ float g_attn[BNT * CH * CH];
__device__ float g_ssq_q[BNT * CH];
__device__ float g_ssq_k[BNT * CH];
__device__ __nv_bfloat16 g_wqkv_h[C3 * KDIM];
__device__ __nv_bfloat16 g_wqkv_l[C3 * KDIM];
__device__ __nv_bfloat16 g_wproj_h[NC * KDIM];
__device__ __nv_bfloat16 g_wproj_l[NC * KDIM];

// ---------------- helpers ----------------
__device__ __forceinline__ uint32_t smem_u32(const void* p) {
    uint32_t a;
    asm("{ .reg .u64 t; cvta.to.shared.u64 t, %1; cvt.u32.u64 %0, t; }" : "=r"(a) : "l"(p));
    return a;
}
__device__ __forceinline__ uint32_t pk_hi(float a, float b) {
    __nv_bfloat16 ha = __float2bfloat16(a), hb = __float2bfloat16(b);
    uint16_t ra = *(uint16_t*)&ha, rb = *(uint16_t*)&hb;
    return (uint32_t)ra | ((uint32_t)rb << 16);
}
__device__ __forceinline__ uint32_t pk_lo(float a, float b) {
    __nv_bfloat16 ha = __float2bfloat16(a), hb = __float2bfloat16(b);
    float la = a - __bfloat162float(ha), lb = b - __bfloat162float(hb);
    __nv_bfloat16 xa = __float2bfloat16(la), xb = __float2bfloat16(lb);
    uint16_t ra = *(uint16_t*)&xa, rb = *(uint16_t*)&xb;
    return (uint32_t)ra | ((uint32_t)rb << 16);
}
__device__ __forceinline__ float bf_lo(uint32_t v) { return __uint_as_float(v << 16); }
__device__ __forceinline__ float bf_hi(uint32_t v) { return __uint_as_float(v & 0xffff0000u); }

__device__ __forceinline__ void mma16816(float* c, const uint32_t* a, const uint32_t* b) {
    asm volatile(
        "mma.sync.aligned.m16n8k16.row.col.f32.bf16.bf16.f32 "
        "{%0,%1,%2,%3}, {%4,%5,%6,%7}, {%8,%9}, {%0,%1,%2,%3};\n"
        : "+f"(c[0]), "+f"(c[1]), "+f"(c[2]), "+f"(c[3])
        : "r"(a[0]), "r"(a[1]), "r"(a[2]), "r"(a[3]), "r"(b[0]), "r"(b[1]));
}
__device__ __forceinline__ void ldmx4(uint32_t* r, uint32_t addr) {
    asm volatile("ldmatrix.sync.aligned.m8n8.x4.shared.b16 {%0,%1,%2,%3}, [%4];"
        : "=r"(r[0]), "=r"(r[1]), "=r"(r[2]), "=r"(r[3]) : "r"(addr));
}
#define CP_ASYNC16(dst, src) asm volatile("cp.async.ca.shared.global [%0], [%1], 16;" :: "r"(dst), "l"(src))
#define CP_COMMIT()          asm volatile("cp.async.commit_group;" ::: "memory")
#define CP_WAIT(n)           asm volatile("cp.async.wait_group %0;" :: "n"(n) : "memory")

// ---------------- weight prep + zero scratch ----------------
__global__ void wprep_kernel(const float* __restrict__ qkvw, const float* __restrict__ projw)
{
    int i = blockIdx.x * 256 + threadIdx.x;
    if (i < C3 * KDIM) {
        int n = i / KDIM, k = i % KDIM;
        float v = qkvw[(size_t)k * C3 + n];
        __nv_bfloat16 h = __float2bfloat16(v);
        g_wqkv_h[i] = h;
        g_wqkv_l[i] = __float2bfloat16(v - __bfloat162float(h));
    }
    if (i < NC * KDIM) {
        int n = i / KDIM, k = i % KDIM;
        float v = projw[(size_t)k * NC + n];
        __nv_bfloat16 h = __float2bfloat16(v);
        g_wproj_h[i] = h;
        g_wproj_l[i] = __float2bfloat16(v - __bfloat162float(h));
    }
    if (i < BNT * CH * CH) g_attn[i] = 0.f;
    if (i < BNT * CH) { g_ssq_q[i] = 0.f; g_ssq_k[i] = 0.f; }
}

// ---------------- mma.sync bf16-split GEMM ----------------
#define ASTRIDE 200
#define ROWB    (ASTRIDE * 2)
#define OFF_AH  0
#define OFF_AL  (128 * ROWB)
#define OFF_B   (2 * 128 * ROWB)
#define BBUF    (64 * ROWB * 2)
#define GEMM_SMEM (OFF_B + 2 * BBUF)

__global__ __launch_bounds__(256) void gemm_mma_split(
    const float* __restrict__ A, const __nv_bfloat16* __restrict__ Wh,
    const __nv_bfloat16* __restrict__ Wl, float* __restrict__ Cout, int Ntot)
{
    extern __shared__ char smem[];
    const uint32_t sbase = smem_u32(smem);
    const uint32_t sAh = sbase + OFF_AH;
    const uint32_t sAl = sbase + OFF_AL;

    const int t = threadIdx.x;
    const int warp = t >> 5, lane = t & 31;
    const int grp = lane >> 2, tig = lane & 3;
    const int warpM = warp >> 1, warpN = warp & 1;
    const size_t m0 = (size_t)blockIdx.x * 128;
    const int nChunks = Ntot >> 6;

    const uint32_t aOff = (uint32_t)(warpM * 32 + (lane & 15)) * ROWB + ((lane >> 4) * 16);
    const uint32_t bOff = (uint32_t)(warpN * 32 + ((lane >> 4) * 8) + (lane & 7)) * ROWB
                          + (((lane >> 3) & 1) * 16);

    {
        const uint4* bh = (const uint4*)Wh;
        const uint4* bl = (const uint4*)Wl;
        uint32_t dsth = sbase + OFF_B;
        uint32_t dstl = dsth + 64 * ROWB;
#pragma unroll
        for (int i = t; i < 1536; i += 256) {
            int row = i / 24, cb = (i % 24) * 16;
            uint32_t o = (uint32_t)row * ROWB + cb;
            CP_ASYNC16(dsth + o, bh + i);
            CP_ASYNC16(dstl + o, bl + i);
        }
        CP_COMMIT();
    }
    {
        int row = t >> 1, half = t & 1;
        const float4* ar = (const float4*)(A + (m0 + row) * KDIM + half * 96);
        __nv_bfloat16* ahp = (__nv_bfloat16*)(smem + OFF_AH) + row * ASTRIDE;
        __nv_bfloat16* alp = (__nv_bfloat16*)(smem + OFF_AL) + row * ASTRIDE;
#pragma unroll
        for (int j = 0; j < 24; j++) {
            float4 v = ar[j];
            int col = half * 96 + j * 4;
            *(uint32_t*)(ahp + col)     = pk_hi(v.x, v.y);
            *(uint32_t*)(ahp + col + 2) = pk_hi(v.z, v.w);
            *(uint32_t*)(alp + col)     = pk_lo(v.x, v.y);
            *(uint32_t*)(alp + col + 2) = pk_lo(v.z, v.w);
        }
    }

    float c[2][4][4];

    for (int nc = 0; nc < nChunks; nc++) {
        if (nc + 1 < nChunks) {
            const uint4* bh = (const uint4*)(Wh + (size_t)(nc + 1) * 64 * KDIM);
            const uint4* bl = (const uint4*)(Wl + (size_t)(nc + 1) * 64 * KDIM);
            uint32_t dsth = sbase + OFF_B + ((nc + 1) & 1) * BBUF;
            uint32_t dstl = dsth + 64 * ROWB;
#pragma unroll
            for (int i = t; i < 1536; i += 256) {
                int row = i / 24, cb = (i % 24) * 16;
                uint32_t o = (uint32_t)row * ROWB + cb;
                CP_ASYNC16(dsth + o, bh + i);
                CP_ASYNC16(dstl + o, bl + i);
            }
            CP_COMMIT();
            CP_WAIT(1);
        } else {
            CP_WAIT(0);
        }
        __syncthreads();

        const uint32_t sBh = sbase + OFF_B + (nc & 1) * BBUF;
        const uint32_t sBl = sBh + 64 * ROWB;

#pragma unroll
        for (int mi = 0; mi < 2; mi++)
#pragma unroll
            for (int ni = 0; ni < 4; ni++)
#pragma unroll
                for (int j = 0; j < 4; j++) c[mi][ni][j] = 0.f;

#pragma unroll
        for (int ks = 0; ks < 12; ks++) {
            const uint32_t k32 = ks * 32;
            uint32_t ah[2][4], al[2][4], bh[2][4], bl[2][4];
            ldmx4(ah[0], sAh + aOff + k32);
            ldmx4(ah[1], sAh + aOff + 16 * ROWB + k32);
            ldmx4(al[0], sAl + aOff + k32);
            ldmx4(al[1], sAl + aOff + 16 * ROWB + k32);
            ldmx4(bh[0], sBh + bOff + k32);
            ldmx4(bh[1], sBh + bOff + 16 * ROWB + k32);
            ldmx4(bl[0], sBl + bOff + k32);
            ldmx4(bl[1], sBl + bOff + 16 * ROWB + k32);
            // three hazard-free sweeps (accumulator reuse distance = 8 mma)
#pragma unroll
            for (int mi = 0; mi < 2; mi++)
#pragma unroll
                for (int p = 0; p < 2; p++) {
                    mma16816(c[mi][2 * p],     ah[mi], &bh[p][0]);
                    mma16816(c[mi][2 * p + 1], ah[mi], &bh[p][2]);
                }
#pragma unroll
            for (int mi = 0; mi < 2; mi++)
#pragma unroll
                for (int p = 0; p < 2; p++) {
                    mma16816(c[mi][2 * p],     ah[mi], &bl[p][0]);
                    mma16816(c[mi][2 * p + 1], ah[mi], &bl[p][2]);
                }
#pragma unroll
            for (int mi = 0; mi < 2; mi++)
#pragma unroll
                for (int p = 0; p < 2; p++) {
                    mma16816(c[mi][2 * p],     al[mi], &bh[p][0]);
                    mma16816(c[mi][2 * p + 1], al[mi], &bh[p][2]);
                }
        }

        const int n0 = nc * 64;
#pragma unroll
        for (int mi = 0; mi < 2; mi++) {
            size_t row = m0 + warpM * 32 + mi * 16 + grp;
#pragma unroll
            for (int ni = 0; ni < 4; ni++) {
                int col = n0 + warpN * 32 + ni * 8 + tig * 2;
                *(float2*)(Cout + row * Ntot + col) = make_float2(c[mi][ni][0], c[mi][ni][1]);
                *(float2*)(Cout + (row + 8) * Ntot + col) = make_float2(c[mi][ni][2], c[mi][ni][3]);
            }
        }
        __syncthreads();
    }
}

// ---------------- smem-tiled depthwise 3x3 + split (q/k -> bf16 hi/lo planes) ----------------
// grid (18 cgroups, 64 tiles, 8 b); block = 256 threads; tile 16x16 px, 8 float4-channels.
__global__ __launch_bounds__(256) void dwconv_tiled_kernel(const float* __restrict__ w)
{
    __shared__ float4 in_t[8][18][18];
    __shared__ float4 wsm[8][9];

    const int cgB = blockIdx.x;              // 0..17
    const int tile = blockIdx.y;             // 0..63
    const int b = blockIdx.z;
    const int ty0 = (tile >> 3) * 16, tx0 = (tile & 7) * 16;
    const int t = threadIdx.x;

    if (t < 72) wsm[t / 9][t % 9] = ((const float4*)w)[(t % 9) * 144 + cgB * 8 + t / 9];

    for (int i = t; i < 2592; i += 256) {
        int c4 = i / 324, rem = i - c4 * 324;
        int py = rem / 18, px = rem - py * 18;
        int gy = ty0 + py - 1, gx = tx0 + px - 1;
        float4 v = make_float4(0.f, 0.f, 0.f, 0.f);
        if ((unsigned)gy < 128u && (unsigned)gx < 128u)
            v = ((const float4*)g_qkv)[((size_t)(b * HH + gy) * WW + gx) * 144 + cgB * 8 + c4];
        in_t[c4][py][px] = v;
    }
    __syncthreads();

    const int plane = cgB / 6;               // 0=q, 1=k, 2=v
    const int py = t >> 4, px = t & 15;
    const size_t p = (size_t)(b * HH + ty0 + py) * WW + tx0 + px;

#pragma unroll
    for (int c4 = 0; c4 < 8; c4++) {
        float4 a = make_float4(0.f, 0.f, 0.f, 0.f);
#pragma unroll
        for (int dy = 0; dy < 3; dy++)
#pragma unroll
            for (int dx = 0; dx < 3; dx++) {
                float4 iv = in_t[c4][py + dy][px + dx];
                float4 wv = wsm[c4][dy * 3 + dx];
                a.x = fmaf(iv.x, wv.x, a.x);
                a.y = fmaf(iv.y, wv.y, a.y);
                a.z = fmaf(iv.z, wv.z, a.z);
                a.w = fmaf(iv.w, wv.w, a.w);
            }
        int c = (cgB * 8 + c4) * 4;
        if (plane == 0) {
            int cc = c;
            *(uint2*)&g_qh[p * NC + cc] = make_uint2(pk_hi(a.x, a.y), pk_hi(a.z, a.w));
            *(uint2*)&g_ql[p * NC + cc] = make_uint2(pk_lo(a.x, a.y), pk_lo(a.z, a.w));
        } else if (plane == 1) {
            int cc = c - NC;
            *(uint2*)&g_kh[p * NC + cc] = make_uint2(pk_hi(a.x, a.y), pk_hi(a.z, a.w));
            *(uint2*)&g_kl[p * NC + cc] = make_uint2(pk_lo(a.x, a.y), pk_lo(a.z, a.w));
        } else {
            int cc = c - 2 * NC;
            *(float4*)&g_v[p * NC + cc] = a;
        }
    }
}

// ---------------- QK^T via mma.sync bf16-split + fused ssq ----------------
// grid (32 bn, 8 splits); 256 threads = 8 warps; each warp a 32-s slice of each 256-s stage.
#define QK_PLANE 25344                     // 48 rows * 528 bytes
#define QK_SMEM  (4 * QK_PLANE)            // 101376

__global__ __launch_bounds__(256) void qk_mma_kernel()
{
    extern __shared__ char qsm[];
    const uint32_t sb = smem_u32(qsm);
    const int t = threadIdx.x, lane = t & 31, warp = t >> 5;
    const int grp = lane >> 2, tig = lane & 3;
    const int bn = blockIdx.x;
    const int sbase0 = blockIdx.y * 2048;

    const uint32_t aAddr = sb + (uint32_t)(lane & 15) * 528 + warp * 64 + ((lane >> 4) * 16);
    const uint32_t bAddr = sb + (uint32_t)(((lane >> 4) * 8) + (lane & 7)) * 528 + warp * 64
                           + (((lane >> 3) & 1) * 16);

    float c[3][6][4];
#pragma unroll
    for (int mi = 0; mi < 3; mi++)
#pragma unroll
        for (int nj = 0; nj < 6; nj++)
#pragma unroll
            for (int j = 0; j < 4; j++) c[mi][nj][j] = 0.f;
    float sq[3][2] = {{0.f,0.f},{0.f,0.f},{0.f,0.f}};
    float sk[3][2] = {{0.f,0.f},{0.f,0.f},{0.f,0.f}};

    for (int stage = 0; stage < 8; stage++) {
        const int sbase = sbase0 + stage * 256;
        // stage 48x256 bf16 of each plane via cp.async (16B chunks)
        const __nv_bfloat16* gp0 = g_qh; const __nv_bfloat16* gp1 = g_ql;
        const __nv_bfloat16* gp2 = g_kh; const __nv_bfloat16* gp3 = g_kl;
#pragma unroll
        for (int pl = 0; pl < 4; pl++) {
            const __nv_bfloat16* gp = (pl == 0) ? gp0 : (pl == 1) ? gp1 : (pl == 2) ? gp2 : gp3;
            uint32_t sp = sb + pl * QK_PLANE;
            for (int i = t; i < 1536; i += 256) {
                int r = i >> 5, seg = i & 31;
                const void* src = gp + (((size_t)(bn * 48 + r)) << 14) + sbase + seg * 8;
                CP_ASYNC16(sp + (uint32_t)r * 528 + seg * 16, src);
            }
        }
        CP_COMMIT();
        CP_WAIT(0);
        __syncthreads();

#pragma unroll
        for (int ks = 0; ks < 2; ks++) {
            const uint32_t kb = ks * 32;
            uint32_t ah[3][4], al[3][4], bh[3][4], bl[3][4];
#pragma unroll
            for (int mi = 0; mi < 3; mi++) {
                ldmx4(ah[mi], aAddr + (uint32_t)(mi * 16) * 528 + kb);
                ldmx4(al[mi], aAddr + QK_PLANE + (uint32_t)(mi * 16) * 528 + kb);
            }
#pragma unroll
            for (int pj = 0; pj < 3; pj++) {
                ldmx4(bh[pj], bAddr + 2 * QK_PLANE + (uint32_t)(pj * 16) * 528 + kb);
                ldmx4(bl[pj], bAddr + 3 * QK_PLANE + (uint32_t)(pj * 16) * 528 + kb);
            }
            // fused square-sums from fragments (hi+lo reconstruction)
#pragma unroll
            for (int mi = 0; mi < 3; mi++)
#pragma unroll
                for (int r = 0; r < 4; r++) {
                    float f0 = bf_lo(ah[mi][r]) + bf_lo(al[mi][r]);
                    float f1 = bf_hi(ah[mi][r]) + bf_hi(al[mi][r]);
                    sq[mi][r & 1] = fmaf(f0, f0, fmaf(f1, f1, sq[mi][r & 1]));
                }
#pragma unroll
            for (int pj = 0; pj < 3; pj++)
#pragma unroll
                for (int r = 0; r < 4; r++) {
                    float f0 = bf_lo(bh[pj][r]) + bf_lo(bl[pj][r]);
                    float f1 = bf_hi(bh[pj][r]) + bf_hi(bl[pj][r]);
                    sk[pj][r >> 1] = fmaf(f0, f0, fmaf(f1, f1, sk[pj][r >> 1]));
                }
            // three hazard-free sweeps of 18 mma each
#pragma unroll
            for (int mi = 0; mi < 3; mi++)
#pragma unroll
                for (int pj = 0; pj < 3; pj++) {
                    mma16816(c[mi][2 * pj],     ah[mi], &bh[pj][0]);
                    mma16816(c[mi][2 * pj + 1], ah[mi], &bh[pj][2]);
                }
#pragma unroll
            for (int mi = 0; mi < 3; mi++)
#pragma unroll
                for (int pj = 0; pj < 3; pj++) {
                    mma16816(c[mi][2 * pj],     ah[mi], &bl[pj][0]);
                    mma16816(c[mi][2 * pj + 1], ah[mi], &bl[pj][2]);
                }
#pragma unroll
            for (int mi = 0; mi < 3; mi++)
#pragma unroll
                for (int pj = 0; pj < 3; pj++) {
                    mma16816(c[mi][2 * pj],     al[mi], &bh[pj][0]);
                    mma16816(c[mi][2 * pj + 1], al[mi], &bh[pj][2]);
                }
        }
        __syncthreads();
    }

    // ---- block reduction in smem overlay, then global atomics ----
    float* attn_s = (float*)qsm;         // 2304
    float* ssq_qs = attn_s + 2304;       // 48
    float* ssq_ks = ssq_qs + 48;         // 48
    for (int i = t; i < 2400; i += 256) attn_s[i] = 0.f;
    __syncthreads();

#pragma unroll
    for (int mi = 0; mi < 3; mi++)
#pragma unroll
        for (int nj = 0; nj < 6; nj++) {
            int row = mi * 16 + grp, col = nj * 8 + tig * 2;
            atomicAdd(&attn_s[row * 48 + col],           c[mi][nj][0]);
            atomicAdd(&attn_s[row * 48 + col + 1],       c[mi][nj][1]);
            atomicAdd(&attn_s[(row + 8) * 48 + col],     c[mi][nj][2]);
            atomicAdd(&attn_s[(row + 8) * 48 + col + 1], c[mi][nj][3]);
        }
#pragma unroll
    for (int mi = 0; mi < 3; mi++)
#pragma unroll
        for (int h = 0; h < 2; h++) {
            float v = sq[mi][h];
            v += __shfl_xor_sync(~0u, v, 1);
            v += __shfl_xor_sync(~0u, v, 2);
            if (tig == 0) atomicAdd(&ssq_qs[mi * 16 + h * 8 + grp], v);
            float u = sk[mi][h];
            u += __shfl_xor_sync(~0u, u, 1);
            u += __shfl_xor_sync(~0u, u, 2);
            if (tig == 0) atomicAdd(&ssq_ks[mi * 16 + h * 8 + grp], u);
        }
    __syncthreads();

    for (int i = t; i < 2304; i += 256) atomicAdd(&g_attn[bn * 2304 + i], attn_s[i]);
    if (t < 48) atomicAdd(&g_ssq_q[bn * 48 + t], ssq_qs[t]);
    else if (t < 96) atomicAdd(&g_ssq_k[bn * 48 + t - 48], ssq_ks[t - 48]);
}

// ---------------- softmax with l2-norm scaling + temperature ----------------
__global__ void softmax48_kernel(const float* __restrict__ temp)
{
    int row = blockIdx.x;
    int bn = row / CH;
    int n = bn & (HEADS - 1);
    int l = threadIdx.x;
    float tf = temp[n];
    float iq = rsqrtf(fmaxf(g_ssq_q[row], 1e-12f));
    float* arow = g_attn + (size_t)row * CH;

    float ik0 = rsqrtf(fmaxf(g_ssq_k[bn * CH + l], 1e-12f));
    float v0 = arow[l] * iq * ik0 * tf;
    float v1 = -3.0e38f;
    if (l < 16) {
        float ik1 = rsqrtf(fmaxf(g_ssq_k[bn * CH + l + 32], 1e-12f));
        v1 = arow[l + 32] * iq * ik1 * tf;
    }
    float m = fmaxf(v0, v1);
#pragma unroll
    for (int o = 16; o > 0; o >>= 1) m = fmaxf(m, __shfl_xor_sync(~0u, m, o));
    float e0 = expf(v0 - m);
    float e1 = (l < 16) ? expf(v1 - m) : 0.f;
    float s = e0 + e1;
#pragma unroll
    for (int o = 16; o > 0; o >>= 1) s += __shfl_xor_sync(~0u, s, o);
    float inv = 1.f / s;
    arow[l] = e0 * inv;
    if (l < 16) arow[l + 32] = e1 * inv;
}

// ---------------- out = attn @ V ----------------
__global__ __launch_bounds__(256) void av_kernel()
{
    int bn = blockIdx.x;
    int s2 = blockIdx.y * 256 + threadIdx.x;

    __shared__ float As[CH * CH];
    for (int f = threadIdx.x; f < CH * CH; f += 256) As[f] = g_attn[bn * CH * CH + f];
    __syncthreads();

    const float2* vb = (const float2*)(g_v + (size_t)bn * CH * HW) + s2;
    float2 vr[CH];
#pragma unroll
    for (int e = 0; e < CH; e++) vr[e] = vb[(size_t)e * (HW / 2)];

    float2* ob = (float2*)(g_o + (size_t)bn * CH * HW) + s2;
    for (int d = 0; d < CH; d++) {
        float2 a = make_float2(0.f, 0.f);
#pragma unroll
        for (int e = 0; e < CH; e++) {
            float w = As[d * CH + e];
            a.x = fmaf(w, vr[e].x, a.x);
            a.y = fmaf(w, vr[e].y, a.y);
        }
        ob[(size_t)d * (HW / 2)] = a;
    }
}

// ---------------- launch ----------------
extern "C" void kernel_launch(void* const* d_in, const int* in_sizes, int n_in,
                              void* d_out, int out_size)
{
    const float* x      = (const float*)d_in[0];
    const float* qkv_w  = (const float*)d_in[1];
    const float* dw_w   = (const float*)d_in[2];
    const float* proj_w = (const float*)d_in[3];
    const float* temp   = (const float*)d_in[4];
    float* out = (float*)d_out;

    float *qkv_buf, *o_buf;
    cudaGetSymbolAddress((void**)&qkv_buf, g_qkv);
    cudaGetSymbolAddress((void**)&o_buf, g_o);
    __nv_bfloat16 *wqh, *wql, *wph, *wpl;
    cudaGetSymbolAddress((void**)&wqh, g_wqkv_h);
    cudaGetSymbolAddress((void**)&wql, g_wqkv_l);
    cudaGetSymbolAddress((void**)&wph, g_wproj_h);
    cudaGetSymbolAddress((void**)&wpl, g_wproj_l);

    cudaFuncSetAttribute(gemm_mma_split, cudaFuncAttributeMaxDynamicSharedMemorySize, GEMM_SMEM);
    cudaFuncSetAttribute(qk_mma_kernel, cudaFuncAttributeMaxDynamicSharedMemorySize, QK_SMEM);

    const int M = NB * HW;

    // 0) weight transpose + bf16 split + zero scratch
    wprep_kernel<<<(C3 * KDIM + 255) / 256, 256>>>(qkv_w, proj_w);

    // 1) qkv = x @ qkv_w
    gemm_mma_split<<<M / 128, 256, GEMM_SMEM>>>(x, wqh, wql, qkv_buf, C3);

    // 2) depthwise 3x3 (smem-tiled) + split: q,k -> bf16 hi/lo planes, v -> fp32
    dwconv_tiled_kernel<<<dim3(18, 64, NB), 256>>>(dw_w);

    // 3) QK^T (tensor cores) + fused square sums
    qk_mma_kernel<<<dim3(BNT, 8), 256, QK_SMEM>>>();

    // 4) scale + softmax
    softmax48_kernel<<<BNT * CH, 32>>>(temp);

    // 5) out = attn @ V
    av_kernel<<<dim3(BNT, HW / 512), 256>>>();

    // 6) projection
    gemm_mma_split<<<M / 128, 256, GEMM_SMEM>>>(o_buf, wph, wpl, out, NC);
}

// round 6
// speedup vs baseline: 1.4069x; 1.4069x over previous
#include <cuda_runtime.h>
#include <cuda_bf16.h>
#include <math.h>
#include <stdint.h>

#define NB 8
#define HH 128
#define WW 128
#define NC 192
#define C3 576
#define HEADS 4
#define CH 48
#define HW 16384
#define BNT 32
#define KDIM 192

// ---------------- scratch ----------------
__device__ float g_qkv[(size_t)NB * HW * C3];
__device__ __nv_bfloat16 g_qh[(size_t)NB * HW * NC];
__device__ __nv_bfloat16 g_ql[(size_t)NB * HW * NC];
__device__ __nv_bfloat16 g_kh[(size_t)NB * HW * NC];
__device__ __nv_bfloat16 g_kl[(size_t)NB * HW * NC];
__device__ float g_v[(size_t)NB * HW * NC];
__device__ float g_o[(size_t)NB * HW * NC];
__device__ float g_attn[BNT * CH * CH];
__device__ float g_ssq_q[BNT * CH];
__device__ float g_ssq_k[BNT * CH];
__device__ __nv_bfloat16 g_wqkv_h[C3 * KDIM];
__device__ __nv_bfloat16 g_wqkv_l[C3 * KDIM];
__device__ __nv_bfloat16 g_wproj_h[NC * KDIM];
__device__ __nv_bfloat16 g_wproj_l[NC * KDIM];

// ---------------- helpers ----------------
__device__ __forceinline__ uint32_t smem_u32(const void* p) {
    uint32_t a;
    asm("{ .reg .u64 t; cvta.to.shared.u64 t, %1; cvt.u32.u64 %0, t; }" : "=r"(a) : "l"(p));
    return a;
}
__device__ __forceinline__ uint32_t pk_hi(float a, float b) {
    __nv_bfloat16 ha = __float2bfloat16(a), hb = __float2bfloat16(b);
    uint16_t ra = *(uint16_t*)&ha, rb = *(uint16_t*)&hb;
    return (uint32_t)ra | ((uint32_t)rb << 16);
}
__device__ __forceinline__ uint32_t pk_lo(float a, float b) {
    __nv_bfloat16 ha = __float2bfloat16(a), hb = __float2bfloat16(b);
    float la = a - __bfloat162float(ha), lb = b - __bfloat162float(hb);
    __nv_bfloat16 xa = __float2bfloat16(la), xb = __float2bfloat16(lb);
    uint16_t ra = *(uint16_t*)&xa, rb = *(uint16_t*)&xb;
    return (uint32_t)ra | ((uint32_t)rb << 16);
}
__device__ __forceinline__ float bf_lo(uint32_t v) { return __uint_as_float(v << 16); }
__device__ __forceinline__ float bf_hi(uint32_t v) { return __uint_as_float(v & 0xffff0000u); }

__device__ __forceinline__ void mma16816(float* c, const uint32_t* a, const uint32_t* b) {
    asm volatile(
        "mma.sync.aligned.m16n8k16.row.col.f32.bf16.bf16.f32 "
        "{%0,%1,%2,%3}, {%4,%5,%6,%7}, {%8,%9}, {%0,%1,%2,%3};\n"
        : "+f"(c[0]), "+f"(c[1]), "+f"(c[2]), "+f"(c[3])
        : "r"(a[0]), "r"(a[1]), "r"(a[2]), "r"(a[3]), "r"(b[0]), "r"(b[1]));
}
__device__ __forceinline__ void ldmx4(uint32_t* r, uint32_t addr) {
    asm volatile("ldmatrix.sync.aligned.m8n8.x4.shared.b16 {%0,%1,%2,%3}, [%4];"
        : "=r"(r[0]), "=r"(r[1]), "=r"(r[2]), "=r"(r[3]) : "r"(addr));
}
#define CP_ASYNC16(dst, src) asm volatile("cp.async.ca.shared.global [%0], [%1], 16;" :: "r"(dst), "l"(src))
#define CP_COMMIT()          asm volatile("cp.async.commit_group;" ::: "memory")
#define CP_WAIT(n)           asm volatile("cp.async.wait_group %0;" :: "n"(n) : "memory")

// ---------------- weight prep + zero scratch ----------------
__global__ void wprep_kernel(const float* __restrict__ qkvw, const float* __restrict__ projw)
{
    int i = blockIdx.x * 256 + threadIdx.x;
    if (i < C3 * KDIM) {
        int n = i / KDIM, k = i % KDIM;
        float v = qkvw[(size_t)k * C3 + n];
        __nv_bfloat16 h = __float2bfloat16(v);
        g_wqkv_h[i] = h;
        g_wqkv_l[i] = __float2bfloat16(v - __bfloat162float(h));
    }
    if (i < NC * KDIM) {
        int n = i / KDIM, k = i % KDIM;
        float v = projw[(size_t)k * NC + n];
        __nv_bfloat16 h = __float2bfloat16(v);
        g_wproj_h[i] = h;
        g_wproj_l[i] = __float2bfloat16(v - __bfloat162float(h));
    }
    if (i < BNT * CH * CH) g_attn[i] = 0.f;
    if (i < BNT * CH) { g_ssq_q[i] = 0.f; g_ssq_k[i] = 0.f; }
}

// ---------------- mma.sync bf16-split GEMM (R4 version, measured) ----------------
#define ASTRIDE 200
#define ROWB    (ASTRIDE * 2)
#define OFF_AH  0
#define OFF_AL  (128 * ROWB)
#define OFF_B   (2 * 128 * ROWB)
#define BBUF    (64 * ROWB * 2)
#define GEMM_SMEM (OFF_B + 2 * BBUF)

__global__ __launch_bounds__(256) void gemm_mma_split(
    const float* __restrict__ A, const __nv_bfloat16* __restrict__ Wh,
    const __nv_bfloat16* __restrict__ Wl, float* __restrict__ Cout, int Ntot)
{
    extern __shared__ char smem[];
    const uint32_t sbase = smem_u32(smem);
    const uint32_t sAh = sbase + OFF_AH;
    const uint32_t sAl = sbase + OFF_AL;

    const int t = threadIdx.x;
    const int warp = t >> 5, lane = t & 31;
    const int grp = lane >> 2, tig = lane & 3;
    const int warpM = warp >> 1, warpN = warp & 1;
    const size_t m0 = (size_t)blockIdx.x * 128;
    const int nChunks = Ntot >> 6;

    const uint32_t aOff = (uint32_t)(warpM * 32 + (lane & 15)) * ROWB + ((lane >> 4) * 16);
    const uint32_t bOff = (uint32_t)(warpN * 32 + ((lane >> 4) * 8) + (lane & 7)) * ROWB
                          + (((lane >> 3) & 1) * 16);

    {
        const uint4* bh = (const uint4*)Wh;
        const uint4* bl = (const uint4*)Wl;
        uint32_t dsth = sbase + OFF_B;
        uint32_t dstl = dsth + 64 * ROWB;
#pragma unroll
        for (int i = t; i < 1536; i += 256) {
            int row = i / 24, cb = (i % 24) * 16;
            uint32_t o = (uint32_t)row * ROWB + cb;
            CP_ASYNC16(dsth + o, bh + i);
            CP_ASYNC16(dstl + o, bl + i);
        }
        CP_COMMIT();
    }
    {
        int row = t >> 1, half = t & 1;
        const float4* ar = (const float4*)(A + (m0 + row) * KDIM + half * 96);
        __nv_bfloat16* ahp = (__nv_bfloat16*)(smem + OFF_AH) + row * ASTRIDE;
        __nv_bfloat16* alp = (__nv_bfloat16*)(smem + OFF_AL) + row * ASTRIDE;
#pragma unroll
        for (int j = 0; j < 24; j++) {
            float4 v = ar[j];
            int col = half * 96 + j * 4;
            *(uint32_t*)(ahp + col)     = pk_hi(v.x, v.y);
            *(uint32_t*)(ahp + col + 2) = pk_hi(v.z, v.w);
            *(uint32_t*)(alp + col)     = pk_lo(v.x, v.y);
            *(uint32_t*)(alp + col + 2) = pk_lo(v.z, v.w);
        }
    }

    float c[2][4][4];

    for (int nc = 0; nc < nChunks; nc++) {
        if (nc + 1 < nChunks) {
            const uint4* bh = (const uint4*)(Wh + (size_t)(nc + 1) * 64 * KDIM);
            const uint4* bl = (const uint4*)(Wl + (size_t)(nc + 1) * 64 * KDIM);
            uint32_t dsth = sbase + OFF_B + ((nc + 1) & 1) * BBUF;
            uint32_t dstl = dsth + 64 * ROWB;
#pragma unroll
            for (int i = t; i < 1536; i += 256) {
                int row = i / 24, cb = (i % 24) * 16;
                uint32_t o = (uint32_t)row * ROWB + cb;
                CP_ASYNC16(dsth + o, bh + i);
                CP_ASYNC16(dstl + o, bl + i);
            }
            CP_COMMIT();
            CP_WAIT(1);
        } else {
            CP_WAIT(0);
        }
        __syncthreads();

        const uint32_t sBh = sbase + OFF_B + (nc & 1) * BBUF;
        const uint32_t sBl = sBh + 64 * ROWB;

#pragma unroll
        for (int mi = 0; mi < 2; mi++)
#pragma unroll
            for (int ni = 0; ni < 4; ni++)
#pragma unroll
                for (int j = 0; j < 4; j++) c[mi][ni][j] = 0.f;

#pragma unroll
        for (int ks = 0; ks < 12; ks++) {
            const uint32_t k32 = ks * 32;
            uint32_t ah[2][4], al[2][4], bh[2][4], bl[2][4];
            ldmx4(ah[0], sAh + aOff + k32);
            ldmx4(ah[1], sAh + aOff + 16 * ROWB + k32);
            ldmx4(al[0], sAl + aOff + k32);
            ldmx4(al[1], sAl + aOff + 16 * ROWB + k32);
            ldmx4(bh[0], sBh + bOff + k32);
            ldmx4(bh[1], sBh + bOff + 16 * ROWB + k32);
            ldmx4(bl[0], sBl + bOff + k32);
            ldmx4(bl[1], sBl + bOff + 16 * ROWB + k32);
#pragma unroll
            for (int mi = 0; mi < 2; mi++)
#pragma unroll
                for (int p = 0; p < 2; p++) {
                    mma16816(c[mi][2 * p],     ah[mi], &bh[p][0]);
                    mma16816(c[mi][2 * p + 1], ah[mi], &bh[p][2]);
                    mma16816(c[mi][2 * p],     ah[mi], &bl[p][0]);
                    mma16816(c[mi][2 * p + 1], ah[mi], &bl[p][2]);
                    mma16816(c[mi][2 * p],     al[mi], &bh[p][0]);
                    mma16816(c[mi][2 * p + 1], al[mi], &bh[p][2]);
                }
        }

        const int n0 = nc * 64;
#pragma unroll
        for (int mi = 0; mi < 2; mi++) {
            size_t row = m0 + warpM * 32 + mi * 16 + grp;
#pragma unroll
            for (int ni = 0; ni < 4; ni++) {
                int col = n0 + warpN * 32 + ni * 8 + tig * 2;
                *(float2*)(Cout + row * Ntot + col) = make_float2(c[mi][ni][0], c[mi][ni][1]);
                *(float2*)(Cout + (row + 8) * Ntot + col) = make_float2(c[mi][ni][2], c[mi][ni][3]);
            }
        }
        __syncthreads();
    }
}

// ---------------- depthwise 3x3 SAME + split (naive/coalesced; q/k -> bf16 hi/lo) ----------------
__global__ __launch_bounds__(256) void dwconv_split_kernel(const float* __restrict__ w)
{
    int gid = blockIdx.x * 256 + threadIdx.x;
    int c4 = gid % 144;
    int p = gid / 144;
    int x = p % WW;
    int y = (p / WW) % HH;
    int b = p / HW;
    int c = c4 * 4;

    float4 acc = make_float4(0.f, 0.f, 0.f, 0.f);
#pragma unroll
    for (int dy = -1; dy <= 1; dy++) {
        int yy = y + dy;
        if (yy < 0 || yy >= HH) continue;
#pragma unroll
        for (int dx = -1; dx <= 1; dx++) {
            int xx = x + dx;
            if (xx < 0 || xx >= WW) continue;
            const float4 iv = *(const float4*)(g_qkv + ((size_t)((b * HH + yy) * WW + xx)) * C3 + c);
            const float4 wv = *(const float4*)(w + (size_t)((dy + 1) * 3 + (dx + 1)) * C3 + c);
            acc.x = fmaf(iv.x, wv.x, acc.x);
            acc.y = fmaf(iv.y, wv.y, acc.y);
            acc.z = fmaf(iv.z, wv.z, acc.z);
            acc.w = fmaf(iv.w, wv.w, acc.w);
        }
    }
    if (c < NC) {
        int cc = c;
        *(uint2*)&g_qh[(size_t)p * NC + cc] = make_uint2(pk_hi(acc.x, acc.y), pk_hi(acc.z, acc.w));
        *(uint2*)&g_ql[(size_t)p * NC + cc] = make_uint2(pk_lo(acc.x, acc.y), pk_lo(acc.z, acc.w));
    } else if (c < 2 * NC) {
        int cc = c - NC;
        *(uint2*)&g_kh[(size_t)p * NC + cc] = make_uint2(pk_hi(acc.x, acc.y), pk_hi(acc.z, acc.w));
        *(uint2*)&g_kl[(size_t)p * NC + cc] = make_uint2(pk_lo(acc.x, acc.y), pk_lo(acc.z, acc.w));
    } else {
        int cc = c - 2 * NC;
        *(float4*)&g_v[(size_t)p * NC + cc] = acc;
    }
}

// ---------------- QK^T via mma.sync bf16-split + fused ssq (R5 version, measured) ----------------
#define QK_PLANE 25344                     // 48 rows * 528 bytes
#define QK_SMEM  (4 * QK_PLANE)            // 101376

__global__ __launch_bounds__(256) void qk_mma_kernel()
{
    extern __shared__ char qsm[];
    const uint32_t sb = smem_u32(qsm);
    const int t = threadIdx.x, lane = t & 31, warp = t >> 5;
    const int grp = lane >> 2, tig = lane & 3;
    const int bn = blockIdx.x;
    const int sbase0 = blockIdx.y * 2048;

    const uint32_t aAddr = sb + (uint32_t)(lane & 15) * 528 + warp * 64 + ((lane >> 4) * 16);
    const uint32_t bAddr = sb + (uint32_t)(((lane >> 4) * 8) + (lane & 7)) * 528 + warp * 64
                           + (((lane >> 3) & 1) * 16);

    float c[3][6][4];
#pragma unroll
    for (int mi = 0; mi < 3; mi++)
#pragma unroll
        for (int nj = 0; nj < 6; nj++)
#pragma unroll
            for (int j = 0; j < 4; j++) c[mi][nj][j] = 0.f;
    float sq[3][2] = {{0.f,0.f},{0.f,0.f},{0.f,0.f}};
    float sk[3][2] = {{0.f,0.f},{0.f,0.f},{0.f,0.f}};

    for (int stage = 0; stage < 8; stage++) {
        const int sbase = sbase0 + stage * 256;
        const __nv_bfloat16* gp0 = g_qh; const __nv_bfloat16* gp1 = g_ql;
        const __nv_bfloat16* gp2 = g_kh; const __nv_bfloat16* gp3 = g_kl;
#pragma unroll
        for (int pl = 0; pl < 4; pl++) {
            const __nv_bfloat16* gp = (pl == 0) ? gp0 : (pl == 1) ? gp1 : (pl == 2) ? gp2 : gp3;
            uint32_t sp = sb + pl * QK_PLANE;
            for (int i = t; i < 1536; i += 256) {
                int r = i >> 5, seg = i & 31;
                const void* src = gp + (((size_t)(bn * 48 + r)) << 14) + sbase + seg * 8;
                CP_ASYNC16(sp + (uint32_t)r * 528 + seg * 16, src);
            }
        }
        CP_COMMIT();
        CP_WAIT(0);
        __syncthreads();

#pragma unroll
        for (int ks = 0; ks < 2; ks++) {
            const uint32_t kb = ks * 32;
            uint32_t ah[3][4], al[3][4], bh[3][4], bl[3][4];
#pragma unroll
            for (int mi = 0; mi < 3; mi++) {
                ldmx4(ah[mi], aAddr + (uint32_t)(mi * 16) * 528 + kb);
                ldmx4(al[mi], aAddr + QK_PLANE + (uint32_t)(mi * 16) * 528 + kb);
            }
#pragma unroll
            for (int pj = 0; pj < 3; pj++) {
                ldmx4(bh[pj], bAddr + 2 * QK_PLANE + (uint32_t)(pj * 16) * 528 + kb);
                ldmx4(bl[pj], bAddr + 3 * QK_PLANE + (uint32_t)(pj * 16) * 528 + kb);
            }
#pragma unroll
            for (int mi = 0; mi < 3; mi++)
#pragma unroll
                for (int r = 0; r < 4; r++) {
                    float f0 = bf_lo(ah[mi][r]) + bf_lo(al[mi][r]);
                    float f1 = bf_hi(ah[mi][r]) + bf_hi(al[mi][r]);
                    sq[mi][r & 1] = fmaf(f0, f0, fmaf(f1, f1, sq[mi][r & 1]));
                }
#pragma unroll
            for (int pj = 0; pj < 3; pj++)
#pragma unroll
                for (int r = 0; r < 4; r++) {
                    float f0 = bf_lo(bh[pj][r]) + bf_lo(bl[pj][r]);
                    float f1 = bf_hi(bh[pj][r]) + bf_hi(bl[pj][r]);
                    sk[pj][r >> 1] = fmaf(f0, f0, fmaf(f1, f1, sk[pj][r >> 1]));
                }
#pragma unroll
            for (int mi = 0; mi < 3; mi++)
#pragma unroll
                for (int pj = 0; pj < 3; pj++) {
                    mma16816(c[mi][2 * pj],     ah[mi], &bh[pj][0]);
                    mma16816(c[mi][2 * pj + 1], ah[mi], &bh[pj][2]);
                }
#pragma unroll
            for (int mi = 0; mi < 3; mi++)
#pragma unroll
                for (int pj = 0; pj < 3; pj++) {
                    mma16816(c[mi][2 * pj],     ah[mi], &bl[pj][0]);
                    mma16816(c[mi][2 * pj + 1], ah[mi], &bl[pj][2]);
                }
#pragma unroll
            for (int mi = 0; mi < 3; mi++)
#pragma unroll
                for (int pj = 0; pj < 3; pj++) {
                    mma16816(c[mi][2 * pj],     al[mi], &bh[pj][0]);
                    mma16816(c[mi][2 * pj + 1], al[mi], &bh[pj][2]);
                }
        }
        __syncthreads();
    }

    float* attn_s = (float*)qsm;
    float* ssq_qs = attn_s + 2304;
    float* ssq_ks = ssq_qs + 48;
    for (int i = t; i < 2400; i += 256) attn_s[i] = 0.f;
    __syncthreads();

#pragma unroll
    for (int mi = 0; mi < 3; mi++)
#pragma unroll
        for (int nj = 0; nj < 6; nj++) {
            int row = mi * 16 + grp, col = nj * 8 + tig * 2;
            atomicAdd(&attn_s[row * 48 + col],           c[mi][nj][0]);
            atomicAdd(&attn_s[row * 48 + col + 1],       c[mi][nj][1]);
            atomicAdd(&attn_s[(row + 8) * 48 + col],     c[mi][nj][2]);
            atomicAdd(&attn_s[(row + 8) * 48 + col + 1], c[mi][nj][3]);
        }
#pragma unroll
    for (int mi = 0; mi < 3; mi++)
#pragma unroll
        for (int h = 0; h < 2; h++) {
            float v = sq[mi][h];
            v += __shfl_xor_sync(~0u, v, 1);
            v += __shfl_xor_sync(~0u, v, 2);
            if (tig == 0) atomicAdd(&ssq_qs[mi * 16 + h * 8 + grp], v);
            float u = sk[mi][h];
            u += __shfl_xor_sync(~0u, u, 1);
            u += __shfl_xor_sync(~0u, u, 2);
            if (tig == 0) atomicAdd(&ssq_ks[mi * 16 + h * 8 + grp], u);
        }
    __syncthreads();

    for (int i = t; i < 2304; i += 256) atomicAdd(&g_attn[bn * 2304 + i], attn_s[i]);
    if (t < 48) atomicAdd(&g_ssq_q[bn * 48 + t], ssq_qs[t]);
    else if (t < 96) atomicAdd(&g_ssq_k[bn * 48 + t - 48], ssq_ks[t - 48]);
}

// ---------------- softmax with l2-norm scaling + temperature ----------------
__global__ void softmax48_kernel(const float* __restrict__ temp)
{
    int row = blockIdx.x;
    int bn = row / CH;
    int n = bn & (HEADS - 1);
    int l = threadIdx.x;
    float tf = temp[n];
    float iq = rsqrtf(fmaxf(g_ssq_q[row], 1e-12f));
    float* arow = g_attn + (size_t)row * CH;

    float ik0 = rsqrtf(fmaxf(g_ssq_k[bn * CH + l], 1e-12f));
    float v0 = arow[l] * iq * ik0 * tf;
    float v1 = -3.0e38f;
    if (l < 16) {
        float ik1 = rsqrtf(fmaxf(g_ssq_k[bn * CH + l + 32], 1e-12f));
        v1 = arow[l + 32] * iq * ik1 * tf;
    }
    float m = fmaxf(v0, v1);
#pragma unroll
    for (int o = 16; o > 0; o >>= 1) m = fmaxf(m, __shfl_xor_sync(~0u, m, o));
    float e0 = expf(v0 - m);
    float e1 = (l < 16) ? expf(v1 - m) : 0.f;
    float s = e0 + e1;
#pragma unroll
    for (int o = 16; o > 0; o >>= 1) s += __shfl_xor_sync(~0u, s, o);
    float inv = 1.f / s;
    arow[l] = e0 * inv;
    if (l < 16) arow[l + 32] = e1 * inv;
}

// ---------------- out = attn @ V ----------------
__global__ __launch_bounds__(256) void av_kernel()
{
    int bn = blockIdx.x;
    int s2 = blockIdx.y * 256 + threadIdx.x;

    __shared__ float As[CH * CH];
    for (int f = threadIdx.x; f < CH * CH; f += 256) As[f] = g_attn[bn * CH * CH + f];
    __syncthreads();

    const float2* vb = (const float2*)(g_v + (size_t)bn * CH * HW) + s2;
    float2 vr[CH];
#pragma unroll
    for (int e = 0; e < CH; e++) vr[e] = vb[(size_t)e * (HW / 2)];

    float2* ob = (float2*)(g_o + (size_t)bn * CH * HW) + s2;
    for (int d = 0; d < CH; d++) {
        float2 a = make_float2(0.f, 0.f);
#pragma unroll
        for (int e = 0; e < CH; e++) {
            float w = As[d * CH + e];
            a.x = fmaf(w, vr[e].x, a.x);
            a.y = fmaf(w, vr[e].y, a.y);
        }
        ob[(size_t)d * (HW / 2)] = a;
    }
}

// ---------------- launch ----------------
extern "C" void kernel_launch(void* const* d_in, const int* in_sizes, int n_in,
                              void* d_out, int out_size)
{
    const float* x      = (const float*)d_in[0];
    const float* qkv_w  = (const float*)d_in[1];
    const float* dw_w   = (const float*)d_in[2];
    const float* proj_w = (const float*)d_in[3];
    const float* temp   = (const float*)d_in[4];
    float* out = (float*)d_out;

    float *qkv_buf, *o_buf;
    cudaGetSymbolAddress((void**)&qkv_buf, g_qkv);
    cudaGetSymbolAddress((void**)&o_buf, g_o);
    __nv_bfloat16 *wqh, *wql, *wph, *wpl;
    cudaGetSymbolAddress((void**)&wqh, g_wqkv_h);
    cudaGetSymbolAddress((void**)&wql, g_wqkv_l);
    cudaGetSymbolAddress((void**)&wph, g_wproj_h);
    cudaGetSymbolAddress((void**)&wpl, g_wproj_l);

    cudaFuncSetAttribute(gemm_mma_split, cudaFuncAttributeMaxDynamicSharedMemorySize, GEMM_SMEM);
    cudaFuncSetAttribute(qk_mma_kernel, cudaFuncAttributeMaxDynamicSharedMemorySize, QK_SMEM);

    const int M = NB * HW;

    // 0) weight transpose + bf16 split + zero scratch
    wprep_kernel<<<(C3 * KDIM + 255) / 256, 256>>>(qkv_w, proj_w);

    // 1) qkv = x @ qkv_w
    gemm_mma_split<<<M / 128, 256, GEMM_SMEM>>>(x, wqh, wql, qkv_buf, C3);

    // 2) depthwise 3x3 (naive, coalesced) + split: q,k -> bf16 hi/lo, v -> fp32
    dwconv_split_kernel<<<(NB * HW * (C3 / 4)) / 256, 256>>>(dw_w);

    // 3) QK^T (tensor cores) + fused square sums
    qk_mma_kernel<<<dim3(BNT, 8), 256, QK_SMEM>>>();

    // 4) scale + softmax
    softmax48_kernel<<<BNT * CH, 32>>>(temp);

    // 5) out = attn @ V
    av_kernel<<<dim3(BNT, HW / 512), 256>>>();

    // 6) projection
    gemm_mma_split<<<M / 128, 256, GEMM_SMEM>>>(o_buf, wph, wpl, out, NC);
}